// round 11
// baseline (speedup 1.0000x reference)
#include <cuda_runtime.h>
#include <cuda_bf16.h>
#include <cstdint>

#define HIDDEN   1024
#define CODEBOOK 8192
#define NTOK     8192
#define NSPLIT   8
#define BM       128
#define BN       128
#define BKE      64                              // int8 elements per k-chunk (64B rows)
#define KCHUNKS  (HIDDEN / BKE)                  // 16
#define NT_PER_BLOCK ((CODEBOOK / NSPLIT) / BN)  // 8
#define NGLOBAL  (NT_PER_BLOCK * KCHUNKS)        // 128 pipeline steps
#define STAGE_BYTES 32768
#define NSTAGE   3
#define SMEM_TOTAL  (NSTAGE * STAGE_BYTES)       // 96 KB

// ---------- device scratch (no runtime allocation allowed) ----------
__device__ int    g_tok_idx[NTOK];
__device__ int    g_n_active;
__device__ float  g_tsq[NTOK];
__device__ float  g_csq[CODEBOOK];
__device__ float  g_partZ[NSPLIT][NTOK];
__device__ float  g_partS[NSPLIT][NTOK];
__device__ float  g_sA1[NTOK];                   // per-token dequant scale (hs)
__device__ float  g_sA2[NTOK];                   // per-token dequant scale (tgt)
__device__ float  g_sW[CODEBOOK];                // per-codeword scale (W col)
__device__ float  g_sWi[CODEBOOK];               // inverse (quant) scale
__device__ float  g_sCB[CODEBOOK];               // per-codeword scale (codebook)
__device__ float  g_wpart[8][CODEBOOK];          // W col-max partials
__device__ int8_t g_A1q[(size_t)NTOK * HIDDEN];
__device__ int8_t g_A2q[(size_t)NTOK * HIDDEN];
__device__ int8_t g_Wtq[(size_t)CODEBOOK * HIDDEN];  // W^T quantized, K-major
__device__ int8_t g_CBq[(size_t)CODEBOOK * HIDDEN];  // codebook quantized, K-major

// ---------- portable PTX helpers (no 'a'-target features) ----------
#define CP_ASYNC16(saddr, gptr) \
    asm volatile("cp.async.cg.shared.global [%0], [%1], 16;" :: "r"(saddr), "l"(gptr))
#define CP_COMMIT()  asm volatile("cp.async.commit_group;" ::: "memory")
#define CP_WAIT1()   asm volatile("cp.async.wait_group 1;" ::: "memory")

static __device__ __forceinline__ void ldsm4(uint32_t* r, uint32_t a) {
    asm volatile("ldmatrix.sync.aligned.m8n8.x4.shared.b16 {%0,%1,%2,%3}, [%4];"
                 : "=r"(r[0]), "=r"(r[1]), "=r"(r[2]), "=r"(r[3]) : "r"(a));
}
// int8 MMA: m16n8k32, s32 accumulate. Fragment byte layout == bf16 k16 reinterpreted.
static __device__ __forceinline__ void mma_s8(int* c, const uint32_t* a, const uint32_t* b) {
    asm volatile(
        "mma.sync.aligned.m16n8k32.row.col.s32.s8.s8.s32 "
        "{%0,%1,%2,%3}, {%4,%5,%6,%7}, {%8,%9}, {%0,%1,%2,%3};"
        : "+r"(c[0]), "+r"(c[1]), "+r"(c[2]), "+r"(c[3])
        : "r"(a[0]), "r"(a[1]), "r"(a[2]), "r"(a[3]), "r"(b[0]), "r"(b[1]));
}

// ============================================================
// 1) Compact image-token indices (deterministic, 1 block, 1024 thr).
// ============================================================
__global__ void compact_kernel(const int* __restrict__ tti)
{
    __shared__ int sodd;
    __shared__ int wsum[32];
    const int tid = threadIdx.x;
    if (tid == 0) sodd = 0;
    __syncthreads();
    int acc = 0;
#pragma unroll
    for (int i = tid; i < 4096; i += 1024) acc |= ((const int2*)tti)[i].y;
    if (acc) atomicOr(&sodd, 1);
    __syncthreads();
    const int stride = sodd ? 1 : 2;   // int32 vs int64 layout probe

    const int base = tid * 8;
    int flags[8];
    int c = 0;
#pragma unroll
    for (int i = 0; i < 8; ++i) {
        flags[i] = (tti[(base + i) * stride] == 1);
        c += flags[i];
    }
    const int lane = tid & 31, w = tid >> 5;
    int p = c;
#pragma unroll
    for (int m = 1; m < 32; m <<= 1) {
        int t = __shfl_up_sync(0xffffffffu, p, m);
        if (lane >= m) p += t;
    }
    if (lane == 31) wsum[w] = p;
    __syncthreads();
    if (w == 0) {
        int v = wsum[lane];
#pragma unroll
        for (int m = 1; m < 32; m <<= 1) {
            int t = __shfl_up_sync(0xffffffffu, v, m);
            if (lane >= m) v += t;
        }
        wsum[lane] = v;
    }
    __syncthreads();
    const int wexcl = (w == 0) ? 0 : wsum[w - 1];
    int o = wexcl + p - c;
#pragma unroll
    for (int i = 0; i < 8; ++i)
        if (flags[i]) g_tok_idx[o++] = base + i;
    if (tid == 1023) g_n_active = wexcl + p;
}

// ============================================================
// 2) pack_A: gather + per-row absmax quantize to int8 (+fused t_sq)
// ============================================================
__global__ void pack_A_kernel(const float* __restrict__ hs, const float* __restrict__ tgt)
{
    __shared__ float r1[8], r2[8], r3[8];
    const int slot = blockIdx.x;
    const int tid  = threadIdx.x;
    const int k4   = tid * 4;
    char4* o1 = (char4*)(g_A1q + (size_t)slot * HIDDEN + k4);
    char4* o2 = (char4*)(g_A2q + (size_t)slot * HIDDEN + k4);
    if (slot >= g_n_active) {
        char4 z = {0, 0, 0, 0};
        *o1 = z; *o2 = z;
        if (tid == 0) { g_sA1[slot] = 0.f; g_sA2[slot] = 0.f; g_tsq[slot] = 0.f; }
        return;
    }
    size_t r = (size_t)g_tok_idx[slot] * HIDDEN + k4;
    float4 v1 = *(const float4*)(hs + r);
    float4 v2 = *(const float4*)(tgt + r);
    float m1 = fmaxf(fmaxf(fabsf(v1.x), fabsf(v1.y)), fmaxf(fabsf(v1.z), fabsf(v1.w)));
    float m2 = fmaxf(fmaxf(fabsf(v2.x), fabsf(v2.y)), fmaxf(fabsf(v2.z), fabsf(v2.w)));
    float sq = v2.x * v2.x + v2.y * v2.y + v2.z * v2.z + v2.w * v2.w;
#pragma unroll
    for (int m = 16; m; m >>= 1) {
        m1 = fmaxf(m1, __shfl_xor_sync(0xffffffffu, m1, m));
        m2 = fmaxf(m2, __shfl_xor_sync(0xffffffffu, m2, m));
        sq += __shfl_xor_sync(0xffffffffu, sq, m);
    }
    if ((tid & 31) == 0) { r1[tid >> 5] = m1; r2[tid >> 5] = m2; r3[tid >> 5] = sq; }
    __syncthreads();
    float b1 = r1[0], b2 = r2[0];
#pragma unroll
    for (int i = 1; i < 8; ++i) { b1 = fmaxf(b1, r1[i]); b2 = fmaxf(b2, r2[i]); }
    const float i1 = b1 > 0.f ? 127.f / b1 : 0.f;
    const float i2 = b2 > 0.f ? 127.f / b2 : 0.f;
    char4 q1, q2;
    q1.x = (char)__float2int_rn(v1.x * i1); q1.y = (char)__float2int_rn(v1.y * i1);
    q1.z = (char)__float2int_rn(v1.z * i1); q1.w = (char)__float2int_rn(v1.w * i1);
    q2.x = (char)__float2int_rn(v2.x * i2); q2.y = (char)__float2int_rn(v2.y * i2);
    q2.z = (char)__float2int_rn(v2.z * i2); q2.w = (char)__float2int_rn(v2.w * i2);
    *o1 = q1; *o2 = q2;
    if (tid == 0) {
        g_sA1[slot] = b1 * (1.f / 127.f);
        g_sA2[slot] = b2 * (1.f / 127.f);
        float s = 0.f;
#pragma unroll
        for (int i = 0; i < 8; ++i) s += r3[i];
        g_tsq[slot] = s * (1.0f / HIDDEN);
    }
}

// ============================================================
// 3) pack_CB: per-codeword absmax quantize (+fused c_sq)
// ============================================================
__global__ void pack_CB_kernel(const float* __restrict__ cb)
{
    __shared__ float r1[8], r3[8];
    const int c   = blockIdx.x;
    const int tid = threadIdx.x;
    const int k4  = tid * 4;
    float4 v = *(const float4*)(cb + (size_t)c * HIDDEN + k4);
    float m1 = fmaxf(fmaxf(fabsf(v.x), fabsf(v.y)), fmaxf(fabsf(v.z), fabsf(v.w)));
    float sq = v.x * v.x + v.y * v.y + v.z * v.z + v.w * v.w;
#pragma unroll
    for (int m = 16; m; m >>= 1) {
        m1 = fmaxf(m1, __shfl_xor_sync(0xffffffffu, m1, m));
        sq += __shfl_xor_sync(0xffffffffu, sq, m);
    }
    if ((tid & 31) == 0) { r1[tid >> 5] = m1; r3[tid >> 5] = sq; }
    __syncthreads();
    float b1 = r1[0];
#pragma unroll
    for (int i = 1; i < 8; ++i) b1 = fmaxf(b1, r1[i]);
    const float i1 = b1 > 0.f ? 127.f / b1 : 0.f;
    char4 q;
    q.x = (char)__float2int_rn(v.x * i1); q.y = (char)__float2int_rn(v.y * i1);
    q.z = (char)__float2int_rn(v.z * i1); q.w = (char)__float2int_rn(v.w * i1);
    *(char4*)(g_CBq + (size_t)c * HIDDEN + k4) = q;
    if (tid == 0) {
        g_sCB[c] = b1 * (1.f / 127.f);
        float s = 0.f;
#pragma unroll
        for (int i = 0; i < 8; ++i) s += r3[i];
        g_csq[c] = s;
    }
}

// ============================================================
// 4) W column scales (two stage) + quantizing transpose
// ============================================================
__global__ void wpmax_kernel(const float* __restrict__ W)
{
    const int col = blockIdx.x * 256 + threadIdx.x;
    const int r0  = blockIdx.y * 128;
    float m = 0.f;
#pragma unroll 8
    for (int r = 0; r < 128; ++r)
        m = fmaxf(m, fabsf(W[(size_t)(r0 + r) * CODEBOOK + col]));
    g_wpart[blockIdx.y][col] = m;
}

__global__ void wscale_kernel()
{
    const int col = blockIdx.x * 256 + threadIdx.x;
    float m = 0.f;
#pragma unroll
    for (int i = 0; i < 8; ++i) m = fmaxf(m, g_wpart[i][col]);
    g_sW[col]  = m * (1.f / 127.f);
    g_sWi[col] = m > 0.f ? 127.f / m : 0.f;
}

__global__ void pack_Wt_kernel(const float* __restrict__ W)
{
    __shared__ float t[32][33];
    __shared__ float ssc[32];
    int c0 = blockIdx.x * 32, h0 = blockIdx.y * 32;
    int tx = threadIdx.x, ty = threadIdx.y;       // (32, 8)
#pragma unroll
    for (int j = 0; j < 4; ++j)
        t[ty + 8 * j][tx] = W[(size_t)(h0 + ty + 8 * j) * CODEBOOK + c0 + tx];
    if (ty == 0) ssc[tx] = g_sWi[c0 + tx];
    __syncthreads();
#pragma unroll
    for (int j = 0; j < 4; ++j) {
        int c = ty + 8 * j;
        g_Wtq[(size_t)(c0 + c) * HIDDEN + h0 + tx] =
            (char)__float2int_rn(t[tx][c] * ssc[c]);
    }
}

// ============================================================
// 5) Fused dual-GEMM (int8 IMMA m16n8k32) + softmax-weighted reduce.
//    Same 64B-row smem/swizzle/ldmatrix machinery as bf16 version;
//    bytes reinterpreted, K per step doubles, steps halve.
// ============================================================
__global__ void __launch_bounds__(256, 1)
tdl_imma(const float* __restrict__ bb)
{
    extern __shared__ char smem[];
    const int tid = threadIdx.x;
    const int n_active = g_n_active;
    const int mtile = blockIdx.x;
    if (mtile * BM >= n_active) return;

    const int wid = tid >> 5, lane = tid & 31;
    const int wm = wid & 3, wn = wid >> 2;

    const int8_t* pA1 = g_A1q + (size_t)mtile * BM * HIDDEN;
    const int8_t* pA2 = g_A2q + (size_t)mtile * BM * HIDDEN;
    const int nbase = blockIdx.y * (CODEBOOK / NSPLIT);

    const uint32_t sbase = (uint32_t)__cvta_generic_to_shared(smem);

    // ---- cp.async slot precompute: thread -> (row, 16B chunk) of 128x64B tile ----
    const int rowbase = tid >> 2;                   // 0..63
    const int ch      = tid & 3;                    // 16B chunk in 64B row
    const uint32_t sw = (uint32_t)((ch ^ ((rowbase >> 1) & 3)) << 4);
    const uint32_t soff = (uint32_t)rowbase * 64u + sw;
    const size_t   goff = (size_t)rowbase * HIDDEN + ch * 16;   // int8 elements

    // ---- ldmatrix address precompute (XOR-swizzled 64B rows) ----
    uint32_t offA[2]; int xA[2];
#pragma unroll
    for (int mt = 0; mt < 2; ++mt) {
        int r = wm * 32 + mt * 16 + (lane & 7) + ((lane >> 3) & 1) * 8;
        offA[mt] = (uint32_t)r * 64u; xA[mt] = (r >> 1) & 3;
    }
    const int coffA = lane >> 4;
    uint32_t offB[4]; int xB[4];
#pragma unroll
    for (int j = 0; j < 4; ++j) {
        int r = wn * 64 + j * 16 + (lane & 7) + ((lane >> 4) & 1) * 8;
        offB[j] = (uint32_t)r * 64u; xB[j] = (r >> 1) & 3;
    }
    const int coffB = (lane >> 3) & 1;

    // ---- per-thread row dequant scales (4 token rows) ----
    const int srow = mtile * BM + wm * 32 + (lane >> 2);
    float fA1[4], fA2[4];
    fA1[0] = g_sA1[srow];      fA1[1] = g_sA1[srow + 8];
    fA1[2] = g_sA1[srow + 16]; fA1[3] = g_sA1[srow + 24];
    fA2[0] = g_sA2[srow];      fA2[1] = g_sA2[srow + 8];
    fA2[2] = g_sA2[srow + 16]; fA2[3] = g_sA2[srow + 24];

    float Zr[4], Sr[4];
#pragma unroll
    for (int r = 0; r < 4; ++r) { Zr[r] = 0.f; Sr[r] = 0.f; }

    // issue one pipeline step's copies (8 x 16B per thread); ALWAYS commit
    auto issue = [&](int g) {
        if (g < NGLOBAL) {
            const int ntg = g >> 4, kcg = g & 15;
            const int8_t* pB1 = g_Wtq + (size_t)(nbase + ntg * BN) * HIDDEN;
            const int8_t* pB2 = g_CBq + (size_t)(nbase + ntg * BN) * HIDDEN;
            const uint32_t s0 = sbase + (uint32_t)(g % NSTAGE) * STAGE_BYTES;
            const size_t k0 = (size_t)kcg * BKE;
#pragma unroll
            for (int i = 0; i < 8; ++i) {
                const int8_t* mp = (i < 2) ? pA1 : (i < 4) ? pA2 : (i < 6) ? pB1 : pB2;
                const int8_t* gp = mp + goff + ((i & 1) ? (size_t)64 * HIDDEN : 0) + k0;
                CP_ASYNC16(s0 + (uint32_t)(i >> 1) * 8192u + soff + ((i & 1) ? 4096u : 0u), gp);
            }
        }
        CP_COMMIT();
    };

    issue(0);
    issue(1);

    int acc1[64], acc2[64];

#pragma unroll 1
    for (int g = 0; g < NGLOBAL; ++g) {
        const int kc = g & 15;
        if (kc == 0) {
#pragma unroll
            for (int i = 0; i < 64; ++i) { acc1[i] = 0; acc2[i] = 0; }
        }
        CP_WAIT1();                 // group g complete (g+1 may be in flight)
        __syncthreads();
        issue(g + 2);               // writes stage (g+2)%3 == (g-1)%3, readers done

        const uint32_t sb = sbase + (uint32_t)(g % NSTAGE) * STAGE_BYTES;
#pragma unroll
        for (int s = 0; s < 2; ++s) {         // two k32 halves of the 64B row
            uint32_t a1[2][4], a2[2][4];
#pragma unroll
            for (int mt = 0; mt < 2; ++mt) {
                uint32_t off = offA[mt] + (uint32_t)(((2 * s + coffA) ^ xA[mt]) << 4);
                ldsm4(a1[mt], sb + off);
                ldsm4(a2[mt], sb + 8192u + off);
            }
#pragma unroll
            for (int j = 0; j < 4; ++j) {
                uint32_t off = offB[j] + (uint32_t)(((2 * s + coffB) ^ xB[j]) << 4);
                uint32_t b1[4], b2[4];
                ldsm4(b1, sb + 16384u + off);
                ldsm4(b2, sb + 24576u + off);
#pragma unroll
                for (int mt = 0; mt < 2; ++mt) {
                    mma_s8(&acc1[mt * 32 + (2 * j) * 4],     a1[mt], b1);
                    mma_s8(&acc1[mt * 32 + (2 * j + 1) * 4], a1[mt], b1 + 2);
                    mma_s8(&acc2[mt * 32 + (2 * j) * 4],     a2[mt], b2);
                    mma_s8(&acc2[mt * 32 + (2 * j + 1) * 4], a2[mt], b2 + 2);
                }
            }
        }

        if (kc == 15) {
            // epilogue: dequant + fold 128x128 tile into per-token (Z, S)
            const int n0 = nbase + (g >> 4) * BN;
#pragma unroll
            for (int ntl = 0; ntl < 8; ++ntl) {
                const int c0 = n0 + wn * 64 + ntl * 8 + (lane & 3) * 2;
                const float sw0 = g_sW[c0], sw1 = g_sW[c0 + 1];
                const float t0 = -2.f * g_sCB[c0], t1 = -2.f * g_sCB[c0 + 1];
                const float b0v = __ldg(bb + c0), b1v = __ldg(bb + c0 + 1);
                const float q0 = g_csq[c0], q1 = g_csq[c0 + 1];
#pragma unroll
                for (int mt = 0; mt < 2; ++mt) {
                    const int* i1 = &acc1[mt * 32 + ntl * 4];
                    const int* i2 = &acc2[mt * 32 + ntl * 4];
                    const float ma0 = fA1[mt * 2], ma1 = fA1[mt * 2 + 1];
                    const float mb0 = fA2[mt * 2], mb1 = fA2[mt * 2 + 1];
                    float e0 = __expf(fmaf((float)i1[0], ma0 * sw0, b0v));
                    float e1 = __expf(fmaf((float)i1[1], ma0 * sw1, b1v));
                    float v0 = fmaf((float)i2[0], mb0 * t0, q0);
                    float v1 = fmaf((float)i2[1], mb0 * t1, q1);
                    Zr[mt * 2 + 0] += e0 + e1;
                    Sr[mt * 2 + 0] += e0 * v0 + e1 * v1;
                    float e2 = __expf(fmaf((float)i1[2], ma1 * sw0, b0v));
                    float e3 = __expf(fmaf((float)i1[3], ma1 * sw1, b1v));
                    float v2 = fmaf((float)i2[2], mb1 * t0, q0);
                    float v3 = fmaf((float)i2[3], mb1 * t1, q1);
                    Zr[mt * 2 + 1] += e2 + e3;
                    Sr[mt * 2 + 1] += e2 * v2 + e3 * v3;
                }
            }
        }
    }

    // ---- reduce across the 4 lanes sharing each row ----
#pragma unroll
    for (int r = 0; r < 4; ++r) {
        Zr[r] += __shfl_xor_sync(0xffffffffu, Zr[r], 1);
        Zr[r] += __shfl_xor_sync(0xffffffffu, Zr[r], 2);
        Sr[r] += __shfl_xor_sync(0xffffffffu, Sr[r], 1);
        Sr[r] += __shfl_xor_sync(0xffffffffu, Sr[r], 2);
    }
    __syncthreads();                    // smem stage area free for reuse
    float* zbuf = (float*)smem;         // [2][128]
    float* sbuf = zbuf + 256;           // [2][128]
    if ((lane & 3) == 0) {
        int gg = lane >> 2;
#pragma unroll
        for (int r = 0; r < 4; ++r) {
            int row = wm * 32 + (r >> 1) * 16 + (r & 1) * 8 + gg;
            zbuf[wn * 128 + row] = Zr[r];
            sbuf[wn * 128 + row] = Sr[r];
        }
    }
    __syncthreads();
    if (tid < 128) {
        int slot = mtile * BM + tid;
        if (slot < n_active) {
            g_partZ[blockIdx.y][slot] = zbuf[tid] + zbuf[128 + tid];
            g_partS[blockIdx.y][slot] = sbuf[tid] + sbuf[128 + tid];
        }
    }
}

// ============================================================
// 6) Final deterministic reduction.
// ============================================================
__global__ void reduce_kernel(float* __restrict__ out)
{
    __shared__ float sm[256];
    const int tid = threadIdx.x;
    const int n = g_n_active;
    float s = 0.f;
    for (int i = tid; i < n; i += 256) {
        float Z = 0.f, S = 0.f;
#pragma unroll
        for (int p = 0; p < NSPLIT; ++p) { Z += g_partZ[p][i]; S += g_partS[p][i]; }
        s += g_tsq[i] + S / (Z * (float)HIDDEN);
    }
    sm[tid] = s;
    __syncthreads();
    for (int m = 128; m; m >>= 1) {
        if (tid < m) sm[tid] += sm[tid + m];
        __syncthreads();
    }
    if (tid == 0) out[0] = sm[0] * 0.1f;
}

// ============================================================
extern "C" void kernel_launch(void* const* d_in, const int* in_sizes, int n_in,
                              void* d_out, int out_size)
{
    (void)in_sizes; (void)n_in; (void)out_size;
    const float* hs  = (const float*)d_in[0];
    const int*   tti = (const int*)  d_in[1];
    const float* tgt = (const float*)d_in[2];
    const float* cb  = (const float*)d_in[3];
    const float* W   = (const float*)d_in[4];
    const float* b   = (const float*)d_in[5];
    float* out = (float*)d_out;

    cudaFuncSetAttribute(tdl_imma, cudaFuncAttributeMaxDynamicSharedMemorySize, SMEM_TOTAL);

    compact_kernel<<<1, 1024>>>(tti);
    pack_A_kernel<<<NTOK, 256>>>(hs, tgt);
    pack_CB_kernel<<<CODEBOOK, 256>>>(cb);
    wpmax_kernel<<<dim3(CODEBOOK / 256, 8), 256>>>(W);
    wscale_kernel<<<CODEBOOK / 256, 256>>>();
    pack_Wt_kernel<<<dim3(CODEBOOK / 32, HIDDEN / 32), dim3(32, 8)>>>(W);

    dim3 grid(NTOK / BM, NSPLIT);
    tdl_imma<<<grid, 256, SMEM_TOTAL>>>(b);
    reduce_kernel<<<1, 256>>>(out);
}

// round 12
// speedup vs baseline: 2.1074x; 2.1074x over previous
#include <cuda_runtime.h>
#include <cuda_bf16.h>
#include <cstdint>

#define HIDDEN   1024
#define CODEBOOK 8192
#define NTOK     8192
#define NSPLIT   4
#define BM       128
#define BN       128
#define BK       32
#define KCHUNKS  (HIDDEN / BK)                  // 32
#define NT_PER_BLOCK ((CODEBOOK / NSPLIT) / BN) // 16
#define NGLOBAL  (NT_PER_BLOCK * KCHUNKS)       // 512 pipeline steps
#define STAGE_BYTES 32768
#define NSTAGE   3
#define SMEM_TOTAL  (NSTAGE * STAGE_BYTES)      // 96 KB

// ---------- device scratch (no runtime allocation allowed) ----------
__device__ int   g_tok_idx[NTOK];
__device__ int   g_n_active;
__device__ float g_tsq[NTOK];
__device__ float g_csq[CODEBOOK];
__device__ float g_partZ[NSPLIT][NTOK];
__device__ float g_partS[NSPLIT][NTOK];
__device__ __nv_bfloat16 g_A1[(size_t)NTOK * HIDDEN];      // hs, compacted
__device__ __nv_bfloat16 g_A2[(size_t)NTOK * HIDDEN];      // tgt, compacted
__device__ __nv_bfloat16 g_Wt[(size_t)CODEBOOK * HIDDEN];  // W transposed (K-major)
__device__ __nv_bfloat16 g_CB[(size_t)CODEBOOK * HIDDEN];  // codebook (K-major)

// ---------- portable PTX helpers (no 'a'-target features) ----------
#define CP_ASYNC16(saddr, gptr) \
    asm volatile("cp.async.cg.shared.global [%0], [%1], 16;" :: "r"(saddr), "l"(gptr))
#define CP_COMMIT()  asm volatile("cp.async.commit_group;" ::: "memory")
#define CP_WAIT1()   asm volatile("cp.async.wait_group 1;" ::: "memory")

static __device__ __forceinline__ void ldsm4(uint32_t* r, uint32_t a) {
    asm volatile("ldmatrix.sync.aligned.m8n8.x4.shared.b16 {%0,%1,%2,%3}, [%4];"
                 : "=r"(r[0]), "=r"(r[1]), "=r"(r[2]), "=r"(r[3]) : "r"(a));
}
static __device__ __forceinline__ void mma16816(float* c, const uint32_t* a, const uint32_t* b) {
    asm volatile(
        "mma.sync.aligned.m16n8k16.row.col.f32.bf16.bf16.f32 "
        "{%0,%1,%2,%3}, {%4,%5,%6,%7}, {%8,%9}, {%0,%1,%2,%3};"
        : "+f"(c[0]), "+f"(c[1]), "+f"(c[2]), "+f"(c[3])
        : "r"(a[0]), "r"(a[1]), "r"(a[2]), "r"(a[3]), "r"(b[0]), "r"(b[1]));
}

// ============================================================
// 1) Compact image-token indices (deterministic, 1 block, 1024 thr).
// ============================================================
__global__ void compact_kernel(const int* __restrict__ tti)
{
    __shared__ int sodd;
    __shared__ int wsum[32];
    const int tid = threadIdx.x;
    if (tid == 0) sodd = 0;
    __syncthreads();
    int acc = 0;
#pragma unroll
    for (int i = tid; i < 4096; i += 1024) acc |= ((const int2*)tti)[i].y;
    if (acc) atomicOr(&sodd, 1);
    __syncthreads();
    const int stride = sodd ? 1 : 2;   // int32 vs int64 layout probe

    const int base = tid * 8;
    int flags[8];
    int c = 0;
#pragma unroll
    for (int i = 0; i < 8; ++i) {
        flags[i] = (tti[(base + i) * stride] == 1);
        c += flags[i];
    }
    const int lane = tid & 31, w = tid >> 5;
    int p = c;
#pragma unroll
    for (int m = 1; m < 32; m <<= 1) {
        int t = __shfl_up_sync(0xffffffffu, p, m);
        if (lane >= m) p += t;
    }
    if (lane == 31) wsum[w] = p;
    __syncthreads();
    if (w == 0) {
        int v = wsum[lane];
#pragma unroll
        for (int m = 1; m < 32; m <<= 1) {
            int t = __shfl_up_sync(0xffffffffu, v, m);
            if (lane >= m) v += t;
        }
        wsum[lane] = v;
    }
    __syncthreads();
    const int wexcl = (w == 0) ? 0 : wsum[w - 1];
    int o = wexcl + p - c;
#pragma unroll
    for (int i = 0; i < 8; ++i)
        if (flags[i]) g_tok_idx[o++] = base + i;
    if (tid == 1023) g_n_active = wexcl + p;
}

// ============================================================
// 2) Fused pack: blocks [0,NTOK) do A(+t_sq); [NTOK,NTOK+CODEBOOK) do CB(+c_sq)
// ============================================================
__global__ void pack_AB_kernel(const float* __restrict__ hs, const float* __restrict__ tgt,
                               const float* __restrict__ cb)
{
    __shared__ float wred[8];
    const int tid = threadIdx.x;
    const int k4  = tid * 4;

    if (blockIdx.x < NTOK) {
        const int slot = blockIdx.x;
        __nv_bfloat162* o1 = (__nv_bfloat162*)(g_A1 + (size_t)slot * HIDDEN + k4);
        __nv_bfloat162* o2 = (__nv_bfloat162*)(g_A2 + (size_t)slot * HIDDEN + k4);
        if (slot >= g_n_active) {
            __nv_bfloat162 z = __floats2bfloat162_rn(0.f, 0.f);
            o1[0] = z; o1[1] = z; o2[0] = z; o2[1] = z;
            return;
        }
        size_t r = (size_t)g_tok_idx[slot] * HIDDEN + k4;
        float4 v1 = *(const float4*)(hs + r);
        float4 v2 = *(const float4*)(tgt + r);
        o1[0] = __floats2bfloat162_rn(v1.x, v1.y);
        o1[1] = __floats2bfloat162_rn(v1.z, v1.w);
        o2[0] = __floats2bfloat162_rn(v2.x, v2.y);
        o2[1] = __floats2bfloat162_rn(v2.z, v2.w);
        float sq = v2.x * v2.x + v2.y * v2.y + v2.z * v2.z + v2.w * v2.w;
#pragma unroll
        for (int m = 16; m; m >>= 1) sq += __shfl_xor_sync(0xffffffffu, sq, m);
        if ((tid & 31) == 0) wred[tid >> 5] = sq;
        __syncthreads();
        if (tid == 0) {
            float s = 0.f;
#pragma unroll
            for (int i = 0; i < 8; ++i) s += wred[i];
            g_tsq[slot] = s * (1.0f / HIDDEN);
        }
    } else {
        const int c = blockIdx.x - NTOK;
        float4 v = *(const float4*)(cb + (size_t)c * HIDDEN + k4);
        __nv_bfloat162* o = (__nv_bfloat162*)(g_CB + (size_t)c * HIDDEN + k4);
        o[0] = __floats2bfloat162_rn(v.x, v.y);
        o[1] = __floats2bfloat162_rn(v.z, v.w);
        float sq = v.x * v.x + v.y * v.y + v.z * v.z + v.w * v.w;
#pragma unroll
        for (int m = 16; m; m >>= 1) sq += __shfl_xor_sync(0xffffffffu, sq, m);
        if ((tid & 31) == 0) wred[tid >> 5] = sq;
        __syncthreads();
        if (tid == 0) {
            float s = 0.f;
#pragma unroll
            for (int i = 0; i < 8; ++i) s += wred[i];
            g_csq[c] = s;
        }
    }
}

__global__ void pack_Wt_kernel(const float* __restrict__ W)
{
    __shared__ float t[32][33];
    int c0 = blockIdx.x * 32, h0 = blockIdx.y * 32;
    int tx = threadIdx.x, ty = threadIdx.y;       // (32, 8)
#pragma unroll
    for (int j = 0; j < 4; ++j)
        t[ty + 8 * j][tx] = W[(size_t)(h0 + ty + 8 * j) * CODEBOOK + c0 + tx];
    __syncthreads();
#pragma unroll
    for (int j = 0; j < 4; ++j)
        g_Wt[(size_t)(c0 + ty + 8 * j) * HIDDEN + h0 + tx] =
            __float2bfloat16_rn(t[tx][ty + 8 * j]);
}

// ============================================================
// 3) Fused dual-GEMM (HMMA bf16) + softmax-weighted reduce.
//    Flattened (nt,kc) pipeline: 3-stage cp.async, ONE sync/step.
//    NSPLIT=4 -> 128 active CTAs = single wave on 148 SMs.
// ============================================================
__global__ void __launch_bounds__(256, 1)
tdl_hmma(const float* __restrict__ bb)
{
    extern __shared__ char smem[];
    const int tid = threadIdx.x;
    const int n_active = g_n_active;
    const int mtile = blockIdx.x;
    if (mtile * BM >= n_active) return;

    const int wid = tid >> 5, lane = tid & 31;
    const int wm = wid & 3, wn = wid >> 2;

    const __nv_bfloat16* pA1 = g_A1 + (size_t)mtile * BM * HIDDEN;
    const __nv_bfloat16* pA2 = g_A2 + (size_t)mtile * BM * HIDDEN;
    const int nbase = blockIdx.y * (CODEBOOK / NSPLIT);

    const uint32_t sbase = (uint32_t)__cvta_generic_to_shared(smem);

    // ---- cp.async slot precompute: thread -> (row, chunk) of a 128x32 tile ----
    const int rowbase = tid >> 2;                   // 0..63
    const int ch      = tid & 3;                    // 16B chunk in 64B row
    const uint32_t sw = (uint32_t)((ch ^ ((rowbase >> 1) & 3)) << 4);
    const uint32_t soff = (uint32_t)rowbase * 64u + sw;
    const size_t   goff = (size_t)rowbase * HIDDEN + ch * 8;

    // ---- ldmatrix address precompute (XOR-swizzled 64B rows) ----
    uint32_t offA[2]; int xA[2];
#pragma unroll
    for (int mt = 0; mt < 2; ++mt) {
        int r = wm * 32 + mt * 16 + (lane & 7) + ((lane >> 3) & 1) * 8;
        offA[mt] = (uint32_t)r * 64u; xA[mt] = (r >> 1) & 3;
    }
    const int coffA = lane >> 4;
    uint32_t offB[4]; int xB[4];
#pragma unroll
    for (int j = 0; j < 4; ++j) {
        int r = wn * 64 + j * 16 + (lane & 7) + ((lane >> 4) & 1) * 8;
        offB[j] = (uint32_t)r * 64u; xB[j] = (r >> 1) & 3;
    }
    const int coffB = (lane >> 3) & 1;

    float Zr[4], Sr[4];
#pragma unroll
    for (int r = 0; r < 4; ++r) { Zr[r] = 0.f; Sr[r] = 0.f; }

    // issue one pipeline step's copies (8 x 16B per thread); ALWAYS commit
    auto issue = [&](int g) {
        if (g < NGLOBAL) {
            const int ntg = g >> 5, kcg = g & 31;
            const __nv_bfloat16* pB1 = g_Wt + (size_t)(nbase + ntg * BN) * HIDDEN;
            const __nv_bfloat16* pB2 = g_CB + (size_t)(nbase + ntg * BN) * HIDDEN;
            const uint32_t s0 = sbase + (uint32_t)(g % NSTAGE) * STAGE_BYTES;
            const size_t k0 = (size_t)kcg * BK;
#pragma unroll
            for (int i = 0; i < 8; ++i) {
                const __nv_bfloat16* mp = (i < 2) ? pA1 : (i < 4) ? pA2 : (i < 6) ? pB1 : pB2;
                const __nv_bfloat16* gp = mp + goff + ((i & 1) ? (size_t)64 * HIDDEN : 0) + k0;
                CP_ASYNC16(s0 + (uint32_t)(i >> 1) * 8192u + soff + ((i & 1) ? 4096u : 0u), gp);
            }
        }
        CP_COMMIT();
    };

    issue(0);
    issue(1);

    float acc1[64], acc2[64];

#pragma unroll 1
    for (int g = 0; g < NGLOBAL; ++g) {
        const int kc = g & 31;
        if (kc == 0) {
#pragma unroll
            for (int i = 0; i < 64; ++i) { acc1[i] = 0.f; acc2[i] = 0.f; }
        }
        CP_WAIT1();                 // group g complete (g+1 may be in flight)
        __syncthreads();
        issue(g + 2);               // writes stage (g+2)%3 == (g-1)%3, readers done

        const uint32_t sb = sbase + (uint32_t)(g % NSTAGE) * STAGE_BYTES;
#pragma unroll
        for (int s = 0; s < 2; ++s) {
            uint32_t a1[2][4], a2[2][4];
#pragma unroll
            for (int mt = 0; mt < 2; ++mt) {
                uint32_t off = offA[mt] + (uint32_t)(((2 * s + coffA) ^ xA[mt]) << 4);
                ldsm4(a1[mt], sb + off);
                ldsm4(a2[mt], sb + 8192u + off);
            }
#pragma unroll
            for (int j = 0; j < 4; ++j) {
                uint32_t off = offB[j] + (uint32_t)(((2 * s + coffB) ^ xB[j]) << 4);
                uint32_t b1[4], b2[4];
                ldsm4(b1, sb + 16384u + off);
                ldsm4(b2, sb + 24576u + off);
#pragma unroll
                for (int mt = 0; mt < 2; ++mt) {
                    mma16816(&acc1[mt * 32 + (2 * j) * 4],     a1[mt], b1);
                    mma16816(&acc1[mt * 32 + (2 * j + 1) * 4], a1[mt], b1 + 2);
                    mma16816(&acc2[mt * 32 + (2 * j) * 4],     a2[mt], b2);
                    mma16816(&acc2[mt * 32 + (2 * j + 1) * 4], a2[mt], b2 + 2);
                }
            }
        }

        if (kc == 31) {
            // epilogue overlaps the already-issued loads of the next tile
            const int n0 = nbase + (g >> 5) * BN;
#pragma unroll
            for (int ntl = 0; ntl < 8; ++ntl) {
                const int c0 = n0 + wn * 64 + ntl * 8 + (lane & 3) * 2;
                const float b0v = __ldg(bb + c0), b1v = __ldg(bb + c0 + 1);
                const float q0 = g_csq[c0], q1 = g_csq[c0 + 1];
#pragma unroll
                for (int mt = 0; mt < 2; ++mt) {
                    const float* a1p = &acc1[mt * 32 + ntl * 4];
                    const float* a2p = &acc2[mt * 32 + ntl * 4];
                    float e0 = __expf(a1p[0] + b0v);
                    float e1 = __expf(a1p[1] + b1v);
                    Zr[mt * 2 + 0] += e0 + e1;
                    Sr[mt * 2 + 0] += e0 * fmaf(-2.f, a2p[0], q0) + e1 * fmaf(-2.f, a2p[1], q1);
                    float e2 = __expf(a1p[2] + b0v);
                    float e3 = __expf(a1p[3] + b1v);
                    Zr[mt * 2 + 1] += e2 + e3;
                    Sr[mt * 2 + 1] += e2 * fmaf(-2.f, a2p[2], q0) + e3 * fmaf(-2.f, a2p[3], q1);
                }
            }
        }
    }

    // ---- reduce across the 4 lanes sharing each row ----
#pragma unroll
    for (int r = 0; r < 4; ++r) {
        Zr[r] += __shfl_xor_sync(0xffffffffu, Zr[r], 1);
        Zr[r] += __shfl_xor_sync(0xffffffffu, Zr[r], 2);
        Sr[r] += __shfl_xor_sync(0xffffffffu, Sr[r], 1);
        Sr[r] += __shfl_xor_sync(0xffffffffu, Sr[r], 2);
    }
    __syncthreads();                    // smem stage area free for reuse
    float* zbuf = (float*)smem;         // [2][128]
    float* sbuf = zbuf + 256;           // [2][128]
    if ((lane & 3) == 0) {
        int gg = lane >> 2;
#pragma unroll
        for (int r = 0; r < 4; ++r) {
            int row = wm * 32 + (r >> 1) * 16 + (r & 1) * 8 + gg;
            zbuf[wn * 128 + row] = Zr[r];
            sbuf[wn * 128 + row] = Sr[r];
        }
    }
    __syncthreads();
    if (tid < 128) {
        int slot = mtile * BM + tid;
        if (slot < n_active) {
            g_partZ[blockIdx.y][slot] = zbuf[tid] + zbuf[128 + tid];
            g_partS[blockIdx.y][slot] = sbuf[tid] + sbuf[128 + tid];
        }
    }
}

// ============================================================
// 4) Final deterministic reduction.
// ============================================================
__global__ void reduce_kernel(float* __restrict__ out)
{
    __shared__ float sm[256];
    const int tid = threadIdx.x;
    const int n = g_n_active;
    float s = 0.f;
    for (int i = tid; i < n; i += 256) {
        float Z = 0.f, S = 0.f;
#pragma unroll
        for (int p = 0; p < NSPLIT; ++p) { Z += g_partZ[p][i]; S += g_partS[p][i]; }
        s += g_tsq[i] + S / (Z * (float)HIDDEN);
    }
    sm[tid] = s;
    __syncthreads();
    for (int m = 128; m; m >>= 1) {
        if (tid < m) sm[tid] += sm[tid + m];
        __syncthreads();
    }
    if (tid == 0) out[0] = sm[0] * 0.1f;
}

// ============================================================
extern "C" void kernel_launch(void* const* d_in, const int* in_sizes, int n_in,
                              void* d_out, int out_size)
{
    (void)in_sizes; (void)n_in; (void)out_size;
    const float* hs  = (const float*)d_in[0];
    const int*   tti = (const int*)  d_in[1];
    const float* tgt = (const float*)d_in[2];
    const float* cb  = (const float*)d_in[3];
    const float* W   = (const float*)d_in[4];
    const float* b   = (const float*)d_in[5];
    float* out = (float*)d_out;

    cudaFuncSetAttribute(tdl_hmma, cudaFuncAttributeMaxDynamicSharedMemorySize, SMEM_TOTAL);

    compact_kernel<<<1, 1024>>>(tti);
    pack_AB_kernel<<<NTOK + CODEBOOK, 256>>>(hs, tgt, cb);
    pack_Wt_kernel<<<dim3(CODEBOOK / 32, HIDDEN / 32), dim3(32, 8)>>>(W);

    dim3 grid(NTOK / BM, NSPLIT);
    tdl_hmma<<<grid, 256, SMEM_TOTAL>>>(b);
    reduce_kernel<<<1, 256>>>(out);
}

// round 14
// speedup vs baseline: 2.6173x; 1.2420x over previous
#include <cuda_runtime.h>
#include <cuda_bf16.h>
#include <cstdint>

#define HIDDEN   1024
#define CODEBOOK 8192
#define NTOK     8192
#define NSPLIT   4
#define BM       128
#define BN       128
#define BK       32
#define KCHUNKS  (HIDDEN / BK)                  // 32
#define NT_PER_BLOCK ((CODEBOOK / NSPLIT) / BN) // 16
#define NGLOBAL  (NT_PER_BLOCK * KCHUNKS)       // 512 pipeline steps
#define STAGE_BYTES 32768
#define NSTAGE   4
#define SMEM_TOTAL  (NSTAGE * STAGE_BYTES)      // 128 KB

// ---------- device scratch (no runtime allocation allowed) ----------
__device__ int   g_tok_idx[NTOK];
__device__ int   g_n_active;
__device__ float g_tsq[NTOK];
__device__ float g_csq[CODEBOOK];
__device__ float g_partZ[NSPLIT][NTOK];
__device__ float g_partS[NSPLIT][NTOK];
__device__ __nv_bfloat16 g_A1[(size_t)NTOK * HIDDEN];      // hs, compacted
__device__ __nv_bfloat16 g_A2[(size_t)NTOK * HIDDEN];      // tgt, compacted
__device__ __nv_bfloat16 g_Wt[(size_t)CODEBOOK * HIDDEN];  // W transposed (K-major)
__device__ __nv_bfloat16 g_CB[(size_t)CODEBOOK * HIDDEN];  // codebook (K-major)

// ---------- portable PTX helpers (no 'a'-target features) ----------
#define CP_ASYNC16(saddr, gptr) \
    asm volatile("cp.async.cg.shared.global [%0], [%1], 16;" :: "r"(saddr), "l"(gptr))
#define CP_COMMIT()  asm volatile("cp.async.commit_group;" ::: "memory")
#define CP_WAIT0()   asm volatile("cp.async.wait_group 0;" ::: "memory")

static __device__ __forceinline__ void ldsm4(uint32_t* r, uint32_t a) {
    asm volatile("ldmatrix.sync.aligned.m8n8.x4.shared.b16 {%0,%1,%2,%3}, [%4];"
                 : "=r"(r[0]), "=r"(r[1]), "=r"(r[2]), "=r"(r[3]) : "r"(a));
}
static __device__ __forceinline__ void mma16816(float* c, const uint32_t* a, const uint32_t* b) {
    asm volatile(
        "mma.sync.aligned.m16n8k16.row.col.f32.bf16.bf16.f32 "
        "{%0,%1,%2,%3}, {%4,%5,%6,%7}, {%8,%9}, {%0,%1,%2,%3};"
        : "+f"(c[0]), "+f"(c[1]), "+f"(c[2]), "+f"(c[3])
        : "r"(a[0]), "r"(a[1]), "r"(a[2]), "r"(a[3]), "r"(b[0]), "r"(b[1]));
}

// ============================================================
// 1) Compact image-token indices (deterministic, 1 block, 1024 thr).
// ============================================================
__global__ void compact_kernel(const int* __restrict__ tti)
{
    __shared__ int sodd;
    __shared__ int wsum[32];
    const int tid = threadIdx.x;
    if (tid == 0) sodd = 0;
    __syncthreads();
    int acc = 0;
#pragma unroll
    for (int i = tid; i < 4096; i += 1024) acc |= ((const int2*)tti)[i].y;
    if (acc) atomicOr(&sodd, 1);
    __syncthreads();
    const int stride = sodd ? 1 : 2;   // int32 vs int64 layout probe

    const int base = tid * 8;
    int flags[8];
    int c = 0;
#pragma unroll
    for (int i = 0; i < 8; ++i) {
        flags[i] = (tti[(base + i) * stride] == 1);
        c += flags[i];
    }
    const int lane = tid & 31, w = tid >> 5;
    int p = c;
#pragma unroll
    for (int m = 1; m < 32; m <<= 1) {
        int t = __shfl_up_sync(0xffffffffu, p, m);
        if (lane >= m) p += t;
    }
    if (lane == 31) wsum[w] = p;
    __syncthreads();
    if (w == 0) {
        int v = wsum[lane];
#pragma unroll
        for (int m = 1; m < 32; m <<= 1) {
            int t = __shfl_up_sync(0xffffffffu, v, m);
            if (lane >= m) v += t;
        }
        wsum[lane] = v;
    }
    __syncthreads();
    const int wexcl = (w == 0) ? 0 : wsum[w - 1];
    int o = wexcl + p - c;
#pragma unroll
    for (int i = 0; i < 8; ++i)
        if (flags[i]) g_tok_idx[o++] = base + i;
    if (tid == 1023) g_n_active = wexcl + p;
}

// ============================================================
// 2) Fused pack: blocks [0,NTOK) do A(+t_sq); [NTOK,NTOK+CODEBOOK) do CB(+c_sq)
// ============================================================
__global__ void pack_AB_kernel(const float* __restrict__ hs, const float* __restrict__ tgt,
                               const float* __restrict__ cb)
{
    __shared__ float wred[8];
    const int tid = threadIdx.x;
    const int k4  = tid * 4;

    if (blockIdx.x < NTOK) {
        const int slot = blockIdx.x;
        __nv_bfloat162* o1 = (__nv_bfloat162*)(g_A1 + (size_t)slot * HIDDEN + k4);
        __nv_bfloat162* o2 = (__nv_bfloat162*)(g_A2 + (size_t)slot * HIDDEN + k4);
        if (slot >= g_n_active) {
            __nv_bfloat162 z = __floats2bfloat162_rn(0.f, 0.f);
            o1[0] = z; o1[1] = z; o2[0] = z; o2[1] = z;
            return;
        }
        size_t r = (size_t)g_tok_idx[slot] * HIDDEN + k4;
        float4 v1 = *(const float4*)(hs + r);
        float4 v2 = *(const float4*)(tgt + r);
        o1[0] = __floats2bfloat162_rn(v1.x, v1.y);
        o1[1] = __floats2bfloat162_rn(v1.z, v1.w);
        o2[0] = __floats2bfloat162_rn(v2.x, v2.y);
        o2[1] = __floats2bfloat162_rn(v2.z, v2.w);
        float sq = v2.x * v2.x + v2.y * v2.y + v2.z * v2.z + v2.w * v2.w;
#pragma unroll
        for (int m = 16; m; m >>= 1) sq += __shfl_xor_sync(0xffffffffu, sq, m);
        if ((tid & 31) == 0) wred[tid >> 5] = sq;
        __syncthreads();
        if (tid == 0) {
            float s = 0.f;
#pragma unroll
            for (int i = 0; i < 8; ++i) s += wred[i];
            g_tsq[slot] = s * (1.0f / HIDDEN);
        }
    } else {
        const int c = blockIdx.x - NTOK;
        float4 v = *(const float4*)(cb + (size_t)c * HIDDEN + k4);
        __nv_bfloat162* o = (__nv_bfloat162*)(g_CB + (size_t)c * HIDDEN + k4);
        o[0] = __floats2bfloat162_rn(v.x, v.y);
        o[1] = __floats2bfloat162_rn(v.z, v.w);
        float sq = v.x * v.x + v.y * v.y + v.z * v.z + v.w * v.w;
#pragma unroll
        for (int m = 16; m; m >>= 1) sq += __shfl_xor_sync(0xffffffffu, sq, m);
        if ((tid & 31) == 0) wred[tid >> 5] = sq;
        __syncthreads();
        if (tid == 0) {
            float s = 0.f;
#pragma unroll
            for (int i = 0; i < 8; ++i) s += wred[i];
            g_csq[c] = s;
        }
    }
}

__global__ void pack_Wt_kernel(const float* __restrict__ W)
{
    __shared__ float t[32][33];
    int c0 = blockIdx.x * 32, h0 = blockIdx.y * 32;
    int tx = threadIdx.x, ty = threadIdx.y;       // (32, 8)
#pragma unroll
    for (int j = 0; j < 4; ++j)
        t[ty + 8 * j][tx] = W[(size_t)(h0 + ty + 8 * j) * CODEBOOK + c0 + tx];
    __syncthreads();
#pragma unroll
    for (int j = 0; j < 4; ++j)
        g_Wt[(size_t)(c0 + ty + 8 * j) * HIDDEN + h0 + tx] =
            __float2bfloat16_rn(t[tx][ty + 8 * j]);
}

// ============================================================
// 3) Fused dual-GEMM (HMMA bf16) + softmax-weighted reduce.
//    4-stage cp.async pipeline, ONE wait+sync per TWO steps,
//    fragment-batched inner loop (load batch hides mma batch).
// ============================================================
__global__ void __launch_bounds__(256, 1)
tdl_hmma(const float* __restrict__ bb)
{
    extern __shared__ char smem[];
    const int tid = threadIdx.x;
    const int n_active = g_n_active;
    const int mtile = blockIdx.x;
    if (mtile * BM >= n_active) return;

    const int wid = tid >> 5, lane = tid & 31;
    const int wm = wid & 3, wn = wid >> 2;

    const __nv_bfloat16* pA1 = g_A1 + (size_t)mtile * BM * HIDDEN;
    const __nv_bfloat16* pA2 = g_A2 + (size_t)mtile * BM * HIDDEN;
    const int nbase = blockIdx.y * (CODEBOOK / NSPLIT);

    const uint32_t sbase = (uint32_t)__cvta_generic_to_shared(smem);

    // ---- cp.async slot precompute: thread -> (row, chunk) of a 128x32 tile ----
    const int rowbase = tid >> 2;                   // 0..63
    const int ch      = tid & 3;                    // 16B chunk in 64B row
    const uint32_t sw = (uint32_t)((ch ^ ((rowbase >> 1) & 3)) << 4);
    const uint32_t soff = (uint32_t)rowbase * 64u + sw;
    const size_t   goff = (size_t)rowbase * HIDDEN + ch * 8;

    // ---- ldmatrix address precompute (XOR-swizzled 64B rows) ----
    uint32_t offA[2]; int xA[2];
#pragma unroll
    for (int mt = 0; mt < 2; ++mt) {
        int r = wm * 32 + mt * 16 + (lane & 7) + ((lane >> 3) & 1) * 8;
        offA[mt] = (uint32_t)r * 64u; xA[mt] = (r >> 1) & 3;
    }
    const int coffA = lane >> 4;
    uint32_t offB[4]; int xB[4];
#pragma unroll
    for (int j = 0; j < 4; ++j) {
        int r = wn * 64 + j * 16 + (lane & 7) + ((lane >> 4) & 1) * 8;
        offB[j] = (uint32_t)r * 64u; xB[j] = (r >> 1) & 3;
    }
    const int coffB = (lane >> 3) & 1;

    float Zr[4], Sr[4];
#pragma unroll
    for (int r = 0; r < 4; ++r) { Zr[r] = 0.f; Sr[r] = 0.f; }

    // issue one pipeline step's copies (8 x 16B per thread); ALWAYS commit
    auto issue = [&](int g) {
        if (g < NGLOBAL) {
            const int ntg = g >> 5, kcg = g & 31;
            const __nv_bfloat16* pB1 = g_Wt + (size_t)(nbase + ntg * BN) * HIDDEN;
            const __nv_bfloat16* pB2 = g_CB + (size_t)(nbase + ntg * BN) * HIDDEN;
            const uint32_t s0 = sbase + (uint32_t)(g % NSTAGE) * STAGE_BYTES;
            const size_t k0 = (size_t)kcg * BK;
#pragma unroll
            for (int i = 0; i < 8; ++i) {
                const __nv_bfloat16* mp = (i < 2) ? pA1 : (i < 4) ? pA2 : (i < 6) ? pB1 : pB2;
                const __nv_bfloat16* gp = mp + goff + ((i & 1) ? (size_t)64 * HIDDEN : 0) + k0;
                CP_ASYNC16(s0 + (uint32_t)(i >> 1) * 8192u + soff + ((i & 1) ? 4096u : 0u), gp);
            }
        }
        CP_COMMIT();
    };

    float acc1[64], acc2[64];

    // one compute sub-step over stage (g % NSTAGE)
    auto compute = [&](int g) {
        const int kc = g & 31;
        if (kc == 0) {
#pragma unroll
            for (int i = 0; i < 64; ++i) { acc1[i] = 0.f; acc2[i] = 0.f; }
        }
        const uint32_t sb = sbase + (uint32_t)(g % NSTAGE) * STAGE_BYTES;
#pragma unroll
        for (int s = 0; s < 2; ++s) {
            // batch-load A fragments (both GEMMs) + all B1 fragments
            uint32_t a1[2][4], a2[2][4], bf[4][4];
#pragma unroll
            for (int mt = 0; mt < 2; ++mt) {
                uint32_t off = offA[mt] + (uint32_t)(((2 * s + coffA) ^ xA[mt]) << 4);
                ldsm4(a1[mt], sb + off);
                ldsm4(a2[mt], sb + 8192u + off);
            }
#pragma unroll
            for (int j = 0; j < 4; ++j) {
                uint32_t off = offB[j] + (uint32_t)(((2 * s + coffB) ^ xB[j]) << 4);
                ldsm4(bf[j], sb + 16384u + off);
            }
            // GEMM1 mma batch (covers B2 fragment-load latency below)
#pragma unroll
            for (int j = 0; j < 4; ++j)
#pragma unroll
                for (int mt = 0; mt < 2; ++mt) {
                    mma16816(&acc1[mt * 32 + (2 * j) * 4],     a1[mt], bf[j]);
                    mma16816(&acc1[mt * 32 + (2 * j + 1) * 4], a1[mt], bf[j] + 2);
                }
            // batch-load all B2 fragments
#pragma unroll
            for (int j = 0; j < 4; ++j) {
                uint32_t off = offB[j] + (uint32_t)(((2 * s + coffB) ^ xB[j]) << 4);
                ldsm4(bf[j], sb + 24576u + off);
            }
            // GEMM2 mma batch
#pragma unroll
            for (int j = 0; j < 4; ++j)
#pragma unroll
                for (int mt = 0; mt < 2; ++mt) {
                    mma16816(&acc2[mt * 32 + (2 * j) * 4],     a2[mt], bf[j]);
                    mma16816(&acc2[mt * 32 + (2 * j + 1) * 4], a2[mt], bf[j] + 2);
                }
        }

        if (kc == 31) {
            // epilogue: fold 128x128 tile into per-token (Z, S)
            const int n0 = nbase + (g >> 5) * BN;
#pragma unroll
            for (int ntl = 0; ntl < 8; ++ntl) {
                const int c0 = n0 + wn * 64 + ntl * 8 + (lane & 3) * 2;
                const float b0v = __ldg(bb + c0), b1v = __ldg(bb + c0 + 1);
                const float q0 = g_csq[c0], q1 = g_csq[c0 + 1];
#pragma unroll
                for (int mt = 0; mt < 2; ++mt) {
                    const float* a1p = &acc1[mt * 32 + ntl * 4];
                    const float* a2p = &acc2[mt * 32 + ntl * 4];
                    float e0 = __expf(a1p[0] + b0v);
                    float e1 = __expf(a1p[1] + b1v);
                    Zr[mt * 2 + 0] += e0 + e1;
                    Sr[mt * 2 + 0] += e0 * fmaf(-2.f, a2p[0], q0) + e1 * fmaf(-2.f, a2p[1], q1);
                    float e2 = __expf(a1p[2] + b0v);
                    float e3 = __expf(a1p[3] + b1v);
                    Zr[mt * 2 + 1] += e2 + e3;
                    Sr[mt * 2 + 1] += e2 * fmaf(-2.f, a2p[2], q0) + e3 * fmaf(-2.f, a2p[3], q1);
                }
            }
        }
    };

    issue(0);
    issue(1);

    // paired steps: one wait+sync per two stages.
    // Pair g reads stages g%4,(g+1)%4 and writes (g+2)%4,(g+3)%4 — the
    // written stages were read in the PREVIOUS pair, whose reads are
    // covered by this pair's __syncthreads (WAR-safe). wait_group 0 at the
    // pair head guarantees groups <= g+1 have landed (RAW-safe + publishes
    // all threads' copies together with the barrier).
#pragma unroll 1
    for (int g = 0; g < NGLOBAL; g += 2) {
        CP_WAIT0();
        __syncthreads();
        issue(g + 2);
        compute(g);
        issue(g + 3);
        compute(g + 1);
    }

    // ---- reduce across the 4 lanes sharing each row ----
#pragma unroll
    for (int r = 0; r < 4; ++r) {
        Zr[r] += __shfl_xor_sync(0xffffffffu, Zr[r], 1);
        Zr[r] += __shfl_xor_sync(0xffffffffu, Zr[r], 2);
        Sr[r] += __shfl_xor_sync(0xffffffffu, Sr[r], 1);
        Sr[r] += __shfl_xor_sync(0xffffffffu, Sr[r], 2);
    }
    __syncthreads();                    // smem stage area free for reuse
    float* zbuf = (float*)smem;         // [2][128]
    float* sbuf = zbuf + 256;           // [2][128]
    if ((lane & 3) == 0) {
        int gg = lane >> 2;
#pragma unroll
        for (int r = 0; r < 4; ++r) {
            int row = wm * 32 + (r >> 1) * 16 + (r & 1) * 8 + gg;
            zbuf[wn * 128 + row] = Zr[r];
            sbuf[wn * 128 + row] = Sr[r];
        }
    }
    __syncthreads();
    if (tid < 128) {
        int slot = mtile * BM + tid;
        if (slot < n_active) {
            g_partZ[blockIdx.y][slot] = zbuf[tid] + zbuf[128 + tid];
            g_partS[blockIdx.y][slot] = sbuf[tid] + sbuf[128 + tid];
        }
    }
}

// ============================================================
// 4) Final deterministic reduction.
// ============================================================
__global__ void reduce_kernel(float* __restrict__ out)
{
    __shared__ float sm[256];
    const int tid = threadIdx.x;
    const int n = g_n_active;
    float s = 0.f;
    for (int i = tid; i < n; i += 256) {
        float Z = 0.f, S = 0.f;
#pragma unroll
        for (int p = 0; p < NSPLIT; ++p) { Z += g_partZ[p][i]; S += g_partS[p][i]; }
        s += g_tsq[i] + S / (Z * (float)HIDDEN);
    }
    sm[tid] = s;
    __syncthreads();
    for (int m = 128; m; m >>= 1) {
        if (tid < m) sm[tid] += sm[tid + m];
        __syncthreads();
    }
    if (tid == 0) out[0] = sm[0] * 0.1f;
}

// ============================================================
extern "C" void kernel_launch(void* const* d_in, const int* in_sizes, int n_in,
                              void* d_out, int out_size)
{
    (void)in_sizes; (void)n_in; (void)out_size;
    const float* hs  = (const float*)d_in[0];
    const int*   tti = (const int*)  d_in[1];
    const float* tgt = (const float*)d_in[2];
    const float* cb  = (const float*)d_in[3];
    const float* W   = (const float*)d_in[4];
    const float* b   = (const float*)d_in[5];
    float* out = (float*)d_out;

    cudaFuncSetAttribute(tdl_hmma, cudaFuncAttributeMaxDynamicSharedMemorySize, SMEM_TOTAL);

    compact_kernel<<<1, 1024>>>(tti);
    pack_AB_kernel<<<NTOK + CODEBOOK, 256>>>(hs, tgt, cb);
    pack_Wt_kernel<<<dim3(CODEBOOK / 32, HIDDEN / 32), dim3(32, 8)>>>(W);

    dim3 grid(NTOK / BM, NSPLIT);
    tdl_hmma<<<grid, 256, SMEM_TOTAL>>>(b);
    reduce_kernel<<<1, 256>>>(out);
}